// round 2
// baseline (speedup 1.0000x reference)
#include <cuda_runtime.h>
#include <math.h>

// Problem constants
#define Qn 8
#define Vn 6890
#define Kn 16
#define En 256
#define Hn 8
#define Dn 32
#define Nn (Qn * Vn)          // 55120 tokens
#define FFN 1024              // 4*E
#define NK (Nn * Kn)          // 881920 edges

// ---------------------------------------------------------------------------
// Scratch (device globals: allocation-free per harness rules)
// ---------------------------------------------------------------------------
__device__ float g_qp[Nn * En];       // q projection  [N,256]
__device__ float g_kp[Nn * En];       // k projection  [N,256]; reused as pre-LN1 buffer
__device__ float g_vp[Nn * En];       // v projection  [N,256]; reused as pre-LN2 buffer
__device__ float g_attn[Nn * En];     // attention output (pre-Wo)
__device__ float g_x[Nn * En];        // post-LN1 activations
__device__ float g_h[Nn * FFN];       // FFN hidden
__device__ int   g_nbr[NK];           // normalized neighbor row index
__device__ unsigned char g_msk[NK];   // normalized mask byte (1 = excluded)
__device__ int   g_flags[2];          // [0]: indices are int64, [1]: mask kind (0=bool,1=int32,2=f32)

// ---------------------------------------------------------------------------
// Detect input dtypes from raw bytes (deterministic; graph-capturable).
// int64 indices  => int32 view has ALL odd words == 0 (values < 2^31).
// int32 mask     => byte view has bytes 1..3 of every word == 0.
// float32 mask   => byte 3 of each word is 0x00 (0.0f) or 0x3f (1.0f).
// ---------------------------------------------------------------------------
__global__ void detect_kernel(const int* __restrict__ bidx32,
                              const unsigned char* __restrict__ mask8)
{
    int idx64 = 1;
    for (int i = 0; i < 2048; i++)
        if (bidx32[2 * i + 1] != 0) { idx64 = 0; break; }

    int all123zero = 1, any3f = 0, bad3 = 0;
    for (int i = 0; i < 2048; i++) {
        unsigned char b1 = mask8[4 * i + 1];
        unsigned char b2 = mask8[4 * i + 2];
        unsigned char b3 = mask8[4 * i + 3];
        if (b1 | b2 | b3) all123zero = 0;
        if (b3 == 0x3f) any3f = 1;
        else if (b3 != 0) bad3 = 1;
    }
    int mkind;
    if (all123zero)           mkind = 1;   // int32 (0/1 values)
    else if (any3f && !bad3)  mkind = 2;   // float32 (0.0/1.0)
    else                      mkind = 0;   // bool bytes
    g_flags[0] = idx64;
    g_flags[1] = mkind;
}

// ---------------------------------------------------------------------------
// Decode indices + mask into normalized scratch.
// ---------------------------------------------------------------------------
__global__ __launch_bounds__(256) void decode_kernel(
    const void* __restrict__ bidx, const void* __restrict__ graph,
    const void* __restrict__ mask)
{
    int i = blockIdx.x * blockDim.x + threadIdx.x;
    if (i >= NK) return;

    long long b, g;
    if (g_flags[0]) {
        b = ((const long long*)bidx)[i];
        g = ((const long long*)graph)[i];
    } else {
        b = ((const int*)bidx)[i];
        g = ((const int*)graph)[i];
    }
    g_nbr[i] = (int)(b * Vn + g);

    unsigned char m;
    int mk = g_flags[1];
    if (mk == 1)      m = (((const int*)mask)[i]   != 0);
    else if (mk == 2) m = (((const float*)mask)[i] != 0.0f);
    else              m = (((const unsigned char*)mask)[i] != 0);
    g_msk[i] = m;
}

// ---------------------------------------------------------------------------
// Tiled SGEMM: C[M,Nc] = A[M,Kd] @ W[Nc,Kd]^T + bias (+ epilogue)
// mode 0: +bias       mode 1: +bias, exact GELU      mode 2: +bias, +residual
// BM=BN=64, BK=16, 256 threads, 4x4 per thread.
// ---------------------------------------------------------------------------
__global__ __launch_bounds__(256) void gemm64_kernel(
    const float* __restrict__ A, const float* __restrict__ W,
    const float* __restrict__ bias, const float* __restrict__ res,
    float* __restrict__ C, int M, int Kd, int Nc, int mode)
{
    __shared__ float As[16][64];   // [k][m]
    __shared__ float Bs[16][64];   // [k][n]

    const int tid  = threadIdx.x;
    const int m0   = blockIdx.x * 64;
    const int n0   = blockIdx.y * 64;
    const int tCol = tid & 15;     // n sub-tile
    const int tRow = tid >> 4;     // m sub-tile
    const int loadRow = tid >> 2;        // 0..63
    const int loadCol = (tid & 3) << 2;  // 0,4,8,12

    float acc[4][4] = {};

    for (int k0 = 0; k0 < Kd; k0 += 16) {
        // Load A tile (guard M), store transposed
        int ar = m0 + loadRow;
        float4 av = make_float4(0.f, 0.f, 0.f, 0.f);
        if (ar < M)
            av = *(const float4*)(A + (size_t)ar * Kd + k0 + loadCol);
        As[loadCol + 0][loadRow] = av.x;
        As[loadCol + 1][loadRow] = av.y;
        As[loadCol + 2][loadRow] = av.z;
        As[loadCol + 3][loadRow] = av.w;

        // Load W tile (Nc multiple of 64, Kd multiple of 16)
        float4 bv = *(const float4*)(W + (size_t)(n0 + loadRow) * Kd + k0 + loadCol);
        Bs[loadCol + 0][loadRow] = bv.x;
        Bs[loadCol + 1][loadRow] = bv.y;
        Bs[loadCol + 2][loadRow] = bv.z;
        Bs[loadCol + 3][loadRow] = bv.w;

        __syncthreads();

        #pragma unroll
        for (int k = 0; k < 16; k++) {
            float4 a4 = *(const float4*)&As[k][tRow << 2];
            float4 b4 = *(const float4*)&Bs[k][tCol << 2];
            float ra[4] = {a4.x, a4.y, a4.z, a4.w};
            float rb[4] = {b4.x, b4.y, b4.z, b4.w};
            #pragma unroll
            for (int i = 0; i < 4; i++)
                #pragma unroll
                for (int j = 0; j < 4; j++)
                    acc[i][j] = fmaf(ra[i], rb[j], acc[i][j]);
        }
        __syncthreads();
    }

    // Epilogue
    #pragma unroll
    for (int i = 0; i < 4; i++) {
        int m = m0 + (tRow << 2) + i;
        if (m >= M) break;
        #pragma unroll
        for (int j = 0; j < 4; j++) {
            int n = n0 + (tCol << 2) + j;
            float v = acc[i][j] + bias[n];
            if (mode == 1) {
                v = 0.5f * v * (1.0f + erff(v * 0.70710678118654752f));
            } else if (mode == 2) {
                v += res[(size_t)m * Nc + n];
            }
            C[(size_t)m * Nc + n] = v;
        }
    }
}

// ---------------------------------------------------------------------------
// Attention: one block per token, one warp per head. K=16 neighbors.
// Reads normalized g_nbr / g_msk scratch.
// ---------------------------------------------------------------------------
__global__ __launch_bounds__(256) void attn_kernel(float* __restrict__ out)
{
    __shared__ int s_nbr[Kn];
    __shared__ int s_msk[Kn];

    const int n   = blockIdx.x;
    const int tid = threadIdx.x;
    if (tid < Kn) {
        s_nbr[tid] = g_nbr[n * Kn + tid];
        s_msk[tid] = (int)g_msk[n * Kn + tid];
    }
    __syncthreads();

    const int h    = tid >> 5;
    const int lane = tid & 31;
    const int base = h * Dn + lane;          // offset within 256-dim row

    const float qd = g_qp[(size_t)n * En + base];

    float sc[Kn];
    #pragma unroll
    for (int k = 0; k < Kn; k++) {
        float p = qd * g_kp[(size_t)s_nbr[k] * En + base];
        #pragma unroll
        for (int off = 16; off; off >>= 1)
            p += __shfl_xor_sync(0xffffffffu, p, off);
        sc[k] = s_msk[k] ? -1e30f : p * 0.17677669529663687f; // 1/sqrt(32)
    }

    float mx = sc[0];
    #pragma unroll
    for (int k = 1; k < Kn; k++) mx = fmaxf(mx, sc[k]);
    float sum = 0.f;
    #pragma unroll
    for (int k = 0; k < Kn; k++) { sc[k] = expf(sc[k] - mx); sum += sc[k]; }
    const float inv = 1.0f / sum;

    float od = 0.f;
    #pragma unroll
    for (int k = 0; k < Kn; k++)
        od += sc[k] * inv * g_vp[(size_t)s_nbr[k] * En + base];

    out[(size_t)n * En + base] = od;
}

// ---------------------------------------------------------------------------
// LayerNorm over last dim (256). One warp per row, 8 rows per block.
// ---------------------------------------------------------------------------
__global__ __launch_bounds__(256) void ln_kernel(
    const float* __restrict__ in, const float* __restrict__ g,
    const float* __restrict__ b, float* __restrict__ out, int M)
{
    const int warp = threadIdx.x >> 5;
    const int lane = threadIdx.x & 31;
    const int row  = blockIdx.x * 8 + warp;
    if (row >= M) return;

    const float* r = in + (size_t)row * En;
    float4 v0 = *(const float4*)(r + lane * 8);
    float4 v1 = *(const float4*)(r + lane * 8 + 4);
    float vals[8] = {v0.x, v0.y, v0.z, v0.w, v1.x, v1.y, v1.z, v1.w};

    float s = 0.f, ss = 0.f;
    #pragma unroll
    for (int i = 0; i < 8; i++) { s += vals[i]; ss += vals[i] * vals[i]; }
    #pragma unroll
    for (int off = 16; off; off >>= 1) {
        s  += __shfl_xor_sync(0xffffffffu, s,  off);
        ss += __shfl_xor_sync(0xffffffffu, ss, off);
    }
    const float mean = s * (1.0f / En);
    const float var  = ss * (1.0f / En) - mean * mean;
    const float rinv = rsqrtf(var + 1e-5f);

    float o[8];
    #pragma unroll
    for (int i = 0; i < 8; i++) {
        int c = lane * 8 + i;
        o[i] = (vals[i] - mean) * rinv * g[c] + b[c];
    }
    float* w = out + (size_t)row * En + lane * 8;
    *(float4*)(w)     = make_float4(o[0], o[1], o[2], o[3]);
    *(float4*)(w + 4) = make_float4(o[4], o[5], o[6], o[7]);
}

// ---------------------------------------------------------------------------
// Launch
// ---------------------------------------------------------------------------
extern "C" void kernel_launch(void* const* d_in, const int* in_sizes, int n_in,
                              void* d_out, int out_size)
{
    const float* X    = (const float*)d_in[0];
    const float* Wq   = (const float*)d_in[1];
    const float* bq   = (const float*)d_in[2];
    const float* Wk   = (const float*)d_in[3];
    const float* bk   = (const float*)d_in[4];
    const float* Wv   = (const float*)d_in[5];
    const float* bv   = (const float*)d_in[6];
    const float* Wo   = (const float*)d_in[7];
    const float* bo   = (const float*)d_in[8];
    const float* ln1g = (const float*)d_in[9];
    const float* ln1b = (const float*)d_in[10];
    const float* W1   = (const float*)d_in[11];
    const float* b1   = (const float*)d_in[12];
    const float* W2   = (const float*)d_in[13];
    const float* b2   = (const float*)d_in[14];
    const float* ln2g = (const float*)d_in[15];
    const float* ln2b = (const float*)d_in[16];
    const void*  bidx = d_in[17];
    const void*  grph = d_in[18];
    const void*  msk  = d_in[19];

    float *qp, *kp, *vp, *attn, *x, *h;
    cudaGetSymbolAddress((void**)&qp,   g_qp);
    cudaGetSymbolAddress((void**)&kp,   g_kp);
    cudaGetSymbolAddress((void**)&vp,   g_vp);
    cudaGetSymbolAddress((void**)&attn, g_attn);
    cudaGetSymbolAddress((void**)&x,    g_x);
    cudaGetSymbolAddress((void**)&h,    g_h);

    // 0) Detect input dtypes, normalize indices + mask into scratch
    detect_kernel<<<1, 1>>>((const int*)bidx, (const unsigned char*)msk);
    decode_kernel<<<(NK + 255) / 256, 256>>>(bidx, grph, msk);

    const int rowBlocks = (Nn + 63) / 64;   // 862

    // 1) Project ALL tokens with Wq/Wk/Wv (gather commutes with linear proj)
    dim3 gP(rowBlocks, En / 64);
    gemm64_kernel<<<gP, 256>>>(X, Wq, bq, nullptr, qp, Nn, En, En, 0);
    gemm64_kernel<<<gP, 256>>>(X, Wk, bk, nullptr, kp, Nn, En, En, 0);
    gemm64_kernel<<<gP, 256>>>(X, Wv, bv, nullptr, vp, Nn, En, En, 0);

    // 2) Attention over gathered projected neighbors
    attn_kernel<<<Nn, 256>>>(attn);

    // 3) o = attn @ Wo^T + bo + residual(X)  -> reuse kp as pre-LN1 buffer
    gemm64_kernel<<<gP, 256>>>(attn, Wo, bo, X, kp, Nn, En, En, 2);

    // 4) x = LN1(kp)
    ln_kernel<<<(Nn + 7) / 8, 256>>>(kp, ln1g, ln1b, x, Nn);

    // 5) h = gelu(x @ W1^T + b1)
    dim3 gF1(rowBlocks, FFN / 64);
    gemm64_kernel<<<gF1, 256>>>(x, W1, b1, nullptr, h, Nn, En, FFN, 1);

    // 6) pre-LN2 = h @ W2^T + b2 + x  -> reuse vp
    gemm64_kernel<<<gP, 256>>>(h, W2, b2, x, vp, Nn, FFN, En, 2);

    // 7) y = LN2(vp) -> d_out
    ln_kernel<<<(Nn + 7) / 8, 256>>>(vp, ln2g, ln2b, (float*)d_out, Nn);
}

// round 3
// speedup vs baseline: 1.3379x; 1.3379x over previous
#include <cuda_runtime.h>
#include <math.h>

// Problem constants
#define Qn 8
#define Vn 6890
#define Kn 16
#define En 256
#define Hn 8
#define Dn 32
#define Nn (Qn * Vn)          // 55120 tokens
#define FFN 1024              // 4*E
#define NK (Nn * Kn)          // 881920 edges
#define QKV 768               // 3*E

// ---------------------------------------------------------------------------
// Scratch (device globals: allocation-free per harness rules)
// ---------------------------------------------------------------------------
__device__ float g_qkv[(size_t)Nn * QKV];   // fused q|k|v projections [N,768]
__device__ float g_attn[(size_t)Nn * En];   // attention out (pre-Wo); reused as pre-LN2
__device__ float g_t1[(size_t)Nn * En];     // pre-LN1 buffer
__device__ float g_x[(size_t)Nn * En];      // post-LN1 activations
__device__ float g_h[(size_t)Nn * FFN];     // FFN hidden
__device__ float g_wqkv[QKV * En];          // concat weights [768,256]
__device__ float g_bqkv[QKV];               // concat bias
__device__ int   g_nbr[NK];                 // neighbor row index
__device__ unsigned char g_msk[NK];         // mask byte (1 = excluded)
__device__ int   g_flags[2];                // [0]: idx int64?  [1]: mask kind

// ---------------------------------------------------------------------------
// Detect input dtypes from raw bytes (parallel, deterministic).
// ---------------------------------------------------------------------------
__global__ __launch_bounds__(256) void detect_kernel(
    const int* __restrict__ bidx32, const unsigned char* __restrict__ mask8)
{
    __shared__ int s_odd, s_b123, s_3f, s_bad3;
    if (threadIdx.x == 0) { s_odd = 0; s_b123 = 0; s_3f = 0; s_bad3 = 0; }
    __syncthreads();

    int oddnz = 0, b123 = 0, f3 = 0, bad = 0;
    for (int i = threadIdx.x; i < 2048; i += 256) {
        if (bidx32[2 * i + 1] != 0) oddnz = 1;
        unsigned char b1 = mask8[4 * i + 1];
        unsigned char b2 = mask8[4 * i + 2];
        unsigned char b3 = mask8[4 * i + 3];
        if (b1 | b2 | b3) b123 = 1;
        if (b3 == 0x3f) f3 = 1; else if (b3 != 0) bad = 1;
    }
    if (oddnz) atomicOr(&s_odd, 1);
    if (b123)  atomicOr(&s_b123, 1);
    if (f3)    atomicOr(&s_3f, 1);
    if (bad)   atomicOr(&s_bad3, 1);
    __syncthreads();
    if (threadIdx.x == 0) {
        g_flags[0] = s_odd ? 0 : 1;                        // int64 iff all odd words zero
        g_flags[1] = (!s_b123) ? 1 : ((s_3f && !s_bad3) ? 2 : 0);
    }
}

// ---------------------------------------------------------------------------
// Decode indices + mask into normalized scratch.
// ---------------------------------------------------------------------------
__global__ __launch_bounds__(256) void decode_kernel(
    const void* __restrict__ bidx, const void* __restrict__ graph,
    const void* __restrict__ mask)
{
    int i = blockIdx.x * blockDim.x + threadIdx.x;
    if (i >= NK) return;

    long long b, g;
    if (g_flags[0]) {
        b = ((const long long*)bidx)[i];
        g = ((const long long*)graph)[i];
    } else {
        b = ((const int*)bidx)[i];
        g = ((const int*)graph)[i];
    }
    g_nbr[i] = (int)(b * Vn + g);

    unsigned char m;
    int mk = g_flags[1];
    if (mk == 1)      m = (((const int*)mask)[i]   != 0);
    else if (mk == 2) m = (((const float*)mask)[i] != 0.0f);
    else              m = (((const unsigned char*)mask)[i] != 0);
    g_msk[i] = m;
}

// ---------------------------------------------------------------------------
// Concatenate Wq|Wk|Wv -> g_wqkv [768,256], bq|bk|bv -> g_bqkv
// ---------------------------------------------------------------------------
__global__ __launch_bounds__(256) void concat_qkv_kernel(
    const float* __restrict__ Wq, const float* __restrict__ Wk,
    const float* __restrict__ Wv, const float* __restrict__ bq,
    const float* __restrict__ bk, const float* __restrict__ bv)
{
    int i = blockIdx.x * blockDim.x + threadIdx.x;
    if (i < En * En) {
        g_wqkv[i]               = Wq[i];
        g_wqkv[En * En + i]     = Wk[i];
        g_wqkv[2 * En * En + i] = Wv[i];
    }
    if (i < En) {
        g_bqkv[i]          = bq[i];
        g_bqkv[En + i]     = bk[i];
        g_bqkv[2 * En + i] = bv[i];
    }
}

// ---------------------------------------------------------------------------
// SGEMM 128x128x16, 256 threads, 8x8/thread, double-buffered smem.
// C[M,Nc] = A[M,Kd] @ W[Nc,Kd]^T + bias (+ epilogue)
// mode 0: +bias   1: +bias, exact GELU   2: +bias, +residual
// ---------------------------------------------------------------------------
__global__ __launch_bounds__(256, 2) void gemm128_kernel(
    const float* __restrict__ A, const float* __restrict__ W,
    const float* __restrict__ bias, const float* __restrict__ res,
    float* __restrict__ C, int M, int Kd, int Nc, int mode)
{
    __shared__ float As[2][16][128];
    __shared__ float Bs[2][16][128];

    const int tid = threadIdx.x;
    const int m0  = blockIdx.x * 128;
    const int n0  = blockIdx.y * 128;

    // Load mapping: each thread loads 2 float4 of A and 2 of B per tile
    const int lr = tid >> 1;           // 0..127 (row of A / row of W)
    const int lk = (tid & 1) << 3;     // 0 or 8

    // Compute mapping: 8 warps as 4x2, warp tile 32x64, thread tile 8x8
    const int warp = tid >> 5;
    const int lane = tid & 31;
    const int tm = ((warp >> 1) << 5) + ((lane >> 3) << 3);  // thread row base
    const int tn = ((warp & 1) << 6) + ((lane & 7) << 3);    // thread col base

    float acc[8][8] = {};

    const float* Aptr = A + (size_t)(m0 + lr) * Kd + lk;
    const float* Wptr = W + (size_t)(n0 + lr) * Kd + lk;
    const bool   aval = (m0 + lr) < M;

    const float4 z4 = make_float4(0.f, 0.f, 0.f, 0.f);
    float4 pa0 = aval ? *(const float4*)(Aptr)     : z4;
    float4 pa1 = aval ? *(const float4*)(Aptr + 4) : z4;
    float4 pb0 = *(const float4*)(Wptr);
    float4 pb1 = *(const float4*)(Wptr + 4);

    const int nt = Kd >> 4;
    int buf = 0;

    // store tile 0
    As[0][lk+0][lr]=pa0.x; As[0][lk+1][lr]=pa0.y; As[0][lk+2][lr]=pa0.z; As[0][lk+3][lr]=pa0.w;
    As[0][lk+4][lr]=pa1.x; As[0][lk+5][lr]=pa1.y; As[0][lk+6][lr]=pa1.z; As[0][lk+7][lr]=pa1.w;
    Bs[0][lk+0][lr]=pb0.x; Bs[0][lk+1][lr]=pb0.y; Bs[0][lk+2][lr]=pb0.z; Bs[0][lk+3][lr]=pb0.w;
    Bs[0][lk+4][lr]=pb1.x; Bs[0][lk+5][lr]=pb1.y; Bs[0][lk+6][lr]=pb1.z; Bs[0][lk+7][lr]=pb1.w;
    __syncthreads();

    for (int t = 0; t < nt; t++) {
        if (t + 1 < nt) {
            const float* Ap = Aptr + ((t + 1) << 4);
            const float* Wp = Wptr + ((t + 1) << 4);
            pa0 = aval ? *(const float4*)(Ap)     : z4;
            pa1 = aval ? *(const float4*)(Ap + 4) : z4;
            pb0 = *(const float4*)(Wp);
            pb1 = *(const float4*)(Wp + 4);
        }

        #pragma unroll
        for (int k = 0; k < 16; k++) {
            float4 a0 = *(const float4*)&As[buf][k][tm];
            float4 a1 = *(const float4*)&As[buf][k][tm + 4];
            float4 b0 = *(const float4*)&Bs[buf][k][tn];
            float4 b1 = *(const float4*)&Bs[buf][k][tn + 4];
            float ra[8] = {a0.x, a0.y, a0.z, a0.w, a1.x, a1.y, a1.z, a1.w};
            float rb[8] = {b0.x, b0.y, b0.z, b0.w, b1.x, b1.y, b1.z, b1.w};
            #pragma unroll
            for (int i = 0; i < 8; i++)
                #pragma unroll
                for (int j = 0; j < 8; j++)
                    acc[i][j] = fmaf(ra[i], rb[j], acc[i][j]);
        }

        if (t + 1 < nt) {
            int nb = buf ^ 1;
            As[nb][lk+0][lr]=pa0.x; As[nb][lk+1][lr]=pa0.y; As[nb][lk+2][lr]=pa0.z; As[nb][lk+3][lr]=pa0.w;
            As[nb][lk+4][lr]=pa1.x; As[nb][lk+5][lr]=pa1.y; As[nb][lk+6][lr]=pa1.z; As[nb][lk+7][lr]=pa1.w;
            Bs[nb][lk+0][lr]=pb0.x; Bs[nb][lk+1][lr]=pb0.y; Bs[nb][lk+2][lr]=pb0.z; Bs[nb][lk+3][lr]=pb0.w;
            Bs[nb][lk+4][lr]=pb1.x; Bs[nb][lk+5][lr]=pb1.y; Bs[nb][lk+6][lr]=pb1.z; Bs[nb][lk+7][lr]=pb1.w;
        }
        __syncthreads();
        buf ^= 1;
    }

    // Epilogue
    float bb[8];
    #pragma unroll
    for (int j = 0; j < 8; j++) bb[j] = bias[n0 + tn + j];

    #pragma unroll
    for (int i = 0; i < 8; i++) {
        int m = m0 + tm + i;
        if (m >= M) continue;
        float v[8];
        #pragma unroll
        for (int j = 0; j < 8; j++) v[j] = acc[i][j] + bb[j];
        if (mode == 1) {
            #pragma unroll
            for (int j = 0; j < 8; j++)
                v[j] = 0.5f * v[j] * (1.0f + erff(v[j] * 0.70710678118654752f));
        } else if (mode == 2) {
            const float* rp = res + (size_t)m * Nc + n0 + tn;
            float4 r0 = *(const float4*)(rp);
            float4 r1 = *(const float4*)(rp + 4);
            v[0]+=r0.x; v[1]+=r0.y; v[2]+=r0.z; v[3]+=r0.w;
            v[4]+=r1.x; v[5]+=r1.y; v[6]+=r1.z; v[7]+=r1.w;
        }
        float* cp = C + (size_t)m * Nc + n0 + tn;
        *(float4*)(cp)     = make_float4(v[0], v[1], v[2], v[3]);
        *(float4*)(cp + 4) = make_float4(v[4], v[5], v[6], v[7]);
    }
}

// ---------------------------------------------------------------------------
// Attention: one block per token, one warp per head. K=16 neighbors.
// Reads fused g_qkv [N,768]: q at +0, k at +256, v at +512.
// ---------------------------------------------------------------------------
__global__ __launch_bounds__(256) void attn_kernel(float* __restrict__ out)
{
    __shared__ int s_nbr[Kn];
    __shared__ int s_msk[Kn];

    const int n   = blockIdx.x;
    const int tid = threadIdx.x;
    if (tid < Kn) {
        s_nbr[tid] = g_nbr[n * Kn + tid];
        s_msk[tid] = (int)g_msk[n * Kn + tid];
    }
    __syncthreads();

    const int h    = tid >> 5;
    const int lane = tid & 31;
    const int base = h * Dn + lane;

    const float qd = g_qkv[(size_t)n * QKV + base];

    float sc[Kn];
    #pragma unroll
    for (int k = 0; k < Kn; k++) {
        float p = qd * g_qkv[(size_t)s_nbr[k] * QKV + En + base];
        #pragma unroll
        for (int off = 16; off; off >>= 1)
            p += __shfl_xor_sync(0xffffffffu, p, off);
        sc[k] = s_msk[k] ? -1e30f : p * 0.17677669529663687f; // 1/sqrt(32)
    }

    float mx = sc[0];
    #pragma unroll
    for (int k = 1; k < Kn; k++) mx = fmaxf(mx, sc[k]);
    float sum = 0.f;
    #pragma unroll
    for (int k = 0; k < Kn; k++) { sc[k] = expf(sc[k] - mx); sum += sc[k]; }
    const float inv = 1.0f / sum;

    float od = 0.f;
    #pragma unroll
    for (int k = 0; k < Kn; k++)
        od += sc[k] * inv * g_qkv[(size_t)s_nbr[k] * QKV + 2 * En + base];

    out[(size_t)n * En + base] = od;
}

// ---------------------------------------------------------------------------
// LayerNorm over last dim (256). One warp per row, 8 rows per block.
// ---------------------------------------------------------------------------
__global__ __launch_bounds__(256) void ln_kernel(
    const float* __restrict__ in, const float* __restrict__ g,
    const float* __restrict__ b, float* __restrict__ out, int M)
{
    const int warp = threadIdx.x >> 5;
    const int lane = threadIdx.x & 31;
    const int row  = blockIdx.x * 8 + warp;
    if (row >= M) return;

    const float* r = in + (size_t)row * En;
    float4 v0 = *(const float4*)(r + lane * 8);
    float4 v1 = *(const float4*)(r + lane * 8 + 4);
    float vals[8] = {v0.x, v0.y, v0.z, v0.w, v1.x, v1.y, v1.z, v1.w};

    float s = 0.f, ss = 0.f;
    #pragma unroll
    for (int i = 0; i < 8; i++) { s += vals[i]; ss += vals[i] * vals[i]; }
    #pragma unroll
    for (int off = 16; off; off >>= 1) {
        s  += __shfl_xor_sync(0xffffffffu, s,  off);
        ss += __shfl_xor_sync(0xffffffffu, ss, off);
    }
    const float mean = s * (1.0f / En);
    const float var  = ss * (1.0f / En) - mean * mean;
    const float rinv = rsqrtf(var + 1e-5f);

    float o[8];
    #pragma unroll
    for (int i = 0; i < 8; i++) {
        int c = lane * 8 + i;
        o[i] = (vals[i] - mean) * rinv * g[c] + b[c];
    }
    float* w = out + (size_t)row * En + lane * 8;
    *(float4*)(w)     = make_float4(o[0], o[1], o[2], o[3]);
    *(float4*)(w + 4) = make_float4(o[4], o[5], o[6], o[7]);
}

// ---------------------------------------------------------------------------
// Launch
// ---------------------------------------------------------------------------
extern "C" void kernel_launch(void* const* d_in, const int* in_sizes, int n_in,
                              void* d_out, int out_size)
{
    const float* X    = (const float*)d_in[0];
    const float* Wq   = (const float*)d_in[1];
    const float* bq   = (const float*)d_in[2];
    const float* Wk   = (const float*)d_in[3];
    const float* bk   = (const float*)d_in[4];
    const float* Wv   = (const float*)d_in[5];
    const float* bv   = (const float*)d_in[6];
    const float* Wo   = (const float*)d_in[7];
    const float* bo   = (const float*)d_in[8];
    const float* ln1g = (const float*)d_in[9];
    const float* ln1b = (const float*)d_in[10];
    const float* W1   = (const float*)d_in[11];
    const float* b1   = (const float*)d_in[12];
    const float* W2   = (const float*)d_in[13];
    const float* b2   = (const float*)d_in[14];
    const float* ln2g = (const float*)d_in[15];
    const float* ln2b = (const float*)d_in[16];
    const void*  bidx = d_in[17];
    const void*  grph = d_in[18];
    const void*  msk  = d_in[19];

    float *qkv, *attn, *t1, *x, *h, *wqkv, *bqkv;
    cudaGetSymbolAddress((void**)&qkv,  g_qkv);
    cudaGetSymbolAddress((void**)&attn, g_attn);
    cudaGetSymbolAddress((void**)&t1,   g_t1);
    cudaGetSymbolAddress((void**)&x,    g_x);
    cudaGetSymbolAddress((void**)&h,    g_h);
    cudaGetSymbolAddress((void**)&wqkv, g_wqkv);
    cudaGetSymbolAddress((void**)&bqkv, g_bqkv);

    // 0) dtype detect + normalize indices/mask; concat QKV weights
    detect_kernel<<<1, 256>>>((const int*)bidx, (const unsigned char*)msk);
    decode_kernel<<<(NK + 255) / 256, 256>>>(bidx, grph, msk);
    concat_qkv_kernel<<<(En * En + 255) / 256, 256>>>(Wq, Wk, Wv, bq, bk, bv);

    const int rb = (Nn + 127) / 128;  // 431

    // 1) fused QKV projection: [N,768]
    gemm128_kernel<<<dim3(rb, QKV / 128), 256>>>(X, wqkv, bqkv, nullptr, qkv, Nn, En, QKV, 0);

    // 2) attention
    attn_kernel<<<Nn, 256>>>(attn);

    // 3) pre-LN1 = attn @ Wo^T + bo + X
    gemm128_kernel<<<dim3(rb, En / 128), 256>>>(attn, Wo, bo, X, t1, Nn, En, En, 2);

    // 4) x = LN1(t1)
    ln_kernel<<<(Nn + 7) / 8, 256>>>(t1, ln1g, ln1b, x, Nn);

    // 5) h = gelu(x @ W1^T + b1)
    gemm128_kernel<<<dim3(rb, FFN / 128), 256>>>(x, W1, b1, nullptr, h, Nn, En, FFN, 1);

    // 6) pre-LN2 = h @ W2^T + b2 + x   (reuse attn buffer)
    gemm128_kernel<<<dim3(rb, En / 128), 256>>>(h, W2, b2, x, attn, Nn, FFN, En, 2);

    // 7) y = LN2 -> d_out
    ln_kernel<<<(Nn + 7) / 8, 256>>>(attn, ln2g, ln2b, (float*)d_out, Nn);
}